// round 12
// baseline (speedup 1.0000x reference)
#include <cuda_runtime.h>
#include <cuda_fp16.h>
#include <cstdint>

#define Bb 32
#define Cc 256
#define Nn 4096
#define N8 512
#define EPSf 1e-5f

// Scratch (device globals — no allocation allowed)
__device__ __half g_qh[(size_t)Bb * N8 * Cc];   // fp16 q (BN+ReLU output)
__device__ __half g_kh[(size_t)Bb * N8 * Cc];   // fp16 k
__device__ float  g_sim[(size_t)Bb * Cc * Cc];  // fp32 sim
__device__ __half g_simh[(size_t)Bb * Cc * Cc]; // fp16 alpha*aff*s
__device__ float  g_pooled[Bb * Cc];
__device__ float  g_s[Bb * Cc];
__device__ __half g_xh[(size_t)Bb * Cc * Nn];   // fp16 copy of x
__device__ __half g_Wqh[(size_t)N8 * Nn];
__device__ __half g_Wkh[(size_t)N8 * Nn];

__device__ __forceinline__ float warpMax(float v) {
#pragma unroll
    for (int o = 16; o; o >>= 1) v = fmaxf(v, __shfl_xor_sync(0xffffffffu, v, o));
    return v;
}
__device__ __forceinline__ float warpSum(float v) {
#pragma unroll
    for (int o = 16; o; o >>= 1) v += __shfl_xor_sync(0xffffffffu, v, o);
    return v;
}

__device__ __forceinline__ void mma_f16(float* c, const uint32_t* a, const uint32_t* b) {
    asm volatile(
        "mma.sync.aligned.m16n8k16.row.col.f32.f16.f16.f32 "
        "{%0,%1,%2,%3}, {%4,%5,%6,%7}, {%8,%9}, {%0,%1,%2,%3};\n"
        : "+f"(c[0]), "+f"(c[1]), "+f"(c[2]), "+f"(c[3])
        : "r"(a[0]), "r"(a[1]), "r"(a[2]), "r"(a[3]), "r"(b[0]), "r"(b[1]));
}
#define LDSM_X4(r0, r1, r2, r3, addr) \
    asm volatile("ldmatrix.sync.aligned.m8n8.x4.shared.b16 {%0,%1,%2,%3}, [%4];" \
                 : "=r"(r0), "=r"(r1), "=r"(r2), "=r"(r3) : "r"(addr))
#define LDSM_X4_T(r0, r1, r2, r3, addr) \
    asm volatile("ldmatrix.sync.aligned.m8n8.x4.trans.shared.b16 {%0,%1,%2,%3}, [%4];" \
                 : "=r"(r0), "=r"(r1), "=r"(r2), "=r"(r3) : "r"(addr))

__device__ __forceinline__ void cp16s(uint32_t saddr, const void* g) {
    asm volatile("cp.async.cg.shared.global [%0], [%1], 16;" :: "r"(saddr), "l"(g));
}
#define CP_COMMIT() asm volatile("cp.async.commit_group;")
#define CP_WAIT2()  asm volatile("cp.async.wait_group 2;")

__device__ __forceinline__ uint32_t smem_u32(const void* p) {
    return (uint32_t)__cvta_generic_to_shared(p);
}

// ---------------------------------------------------------------------------
// Fused prep: blocks [0, Bb*Cc) do pool+x->fp16; the rest convert Wq/Wk.
// ---------------------------------------------------------------------------
#define POOL_BLOCKS (Bb * Cc)
#define CONVW_BLOCKS ((N8 * Nn / 4) / 256)

__global__ void prep_kernel(const float* __restrict__ x,
                            const float* __restrict__ Wq,
                            const float* __restrict__ Wk) {
    if (blockIdx.x < POOL_BLOCKS) {
        int row = blockIdx.x;  // b*Cc + c
        const float4* xr = (const float4*)(x + (size_t)row * Nn);
        uint2* xh = (uint2*)(g_xh + (size_t)row * Nn);
        float m = -3.0e38f;
        for (int i = threadIdx.x; i < Nn / 4; i += 256) {
            float4 v = xr[i];
            __half2 p01 = __floats2half2_rn(v.x, v.y);
            __half2 p23 = __floats2half2_rn(v.z, v.w);
            uint2 u;
            u.x = *reinterpret_cast<uint32_t*>(&p01);
            u.y = *reinterpret_cast<uint32_t*>(&p23);
            xh[i] = u;
            m = fmaxf(m, fmaxf(fmaxf(v.x, v.y), fmaxf(v.z, v.w)));
        }
        m = warpMax(m);
        __shared__ float sm[8];
        if ((threadIdx.x & 31) == 0) sm[threadIdx.x >> 5] = m;
        __syncthreads();
        if (threadIdx.x == 0) {
            float r = sm[0];
#pragma unroll
            for (int i = 1; i < 8; i++) r = fmaxf(r, sm[i]);
            g_pooled[row] = r;
        }
    } else {
        int i = (blockIdx.x - POOL_BLOCKS) * 256 + threadIdx.x;
        float4 q = ((const float4*)Wq)[i];
        float4 k = ((const float4*)Wk)[i];
        __half2 q01 = __floats2half2_rn(q.x, q.y), q23 = __floats2half2_rn(q.z, q.w);
        __half2 k01 = __floats2half2_rn(k.x, k.y), k23 = __floats2half2_rn(k.z, k.w);
        uint2 uq, uk;
        uq.x = *reinterpret_cast<uint32_t*>(&q01); uq.y = *reinterpret_cast<uint32_t*>(&q23);
        uk.x = *reinterpret_cast<uint32_t*>(&k01); uk.y = *reinterpret_cast<uint32_t*>(&k23);
        ((uint2*)g_Wqh)[i] = uq;
        ((uint2*)g_Wkh)[i] = uk;
    }
}

// ---------------------------------------------------------------------------
__global__ void se_kernel(const float* __restrict__ W1, const float* __restrict__ W2) {
    int b = blockIdx.x;
    int t = threadIdx.x;
    __shared__ float h[32];
    if (t < 32) {
        float acc = 0.f;
        const float* w = W1 + t * Cc;
        const float* p = g_pooled + b * Cc;
        for (int c = 0; c < Cc; c++) acc += w[c] * p[c];
        h[t] = fmaxf(acc, 0.f);
    }
    __syncthreads();
    float acc = 0.f;
    const float* w2 = W2 + t * 32;
#pragma unroll
    for (int j = 0; j < 32; j++) acc += w2[j] * h[j];
    g_s[b * Cc + t] = 1.f / (1.f + expf(-acc));
}

// ---------------------------------------------------------------------------
// fp16 q/k GEMM: R8-proven config. Block 128x128, 4 warps of 64x64, kc=32,
// 4-stage cp.async, wait_group 2, LDSM/MMA first, prefetch after, two barriers.
// ---------------------------------------------------------------------------
#define QK_ROWB 80
#define QK_OPB  10240       // 128 rows * 80 B
#define QK_STB  20480
#define QK_NCH  (Nn / 32)   // 128

__global__ __launch_bounds__(128, 2) void gemm_qk_f16(
    const float* __restrict__ gq, const float* __restrict__ bq,
    const float* __restrict__ mq, const float* __restrict__ vq,
    const float* __restrict__ gk, const float* __restrict__ bk,
    const float* __restrict__ mk, const float* __restrict__ vk) {
    extern __shared__ char rawsm[];
    const uint32_t sbase = smem_u32(rawsm);

    const int z = blockIdx.z;
    const int b = z >> 1;
    const int sel = z & 1;
    const int m0 = blockIdx.y * 128;
    const int n0 = blockIdx.x * 128;
    const int tid = threadIdx.x;
    const int lane = tid & 31, warp = tid >> 5;
    const int wm = (warp >> 1) * 64, wn = (warp & 1) * 64;
    const int g = lane >> 2, t4 = lane & 3;

    const int lrow = tid >> 1;
    const int lhalf = tid & 1;
    const __half* gW0 = (sel ? g_Wkh : g_Wqh) + (size_t)(m0 + lrow) * Nn + lhalf * 16;
    const __half* gW1 = gW0 + (size_t)64 * Nn;
    const __half* gX0 = g_xh + ((size_t)b * Cc + n0 + lrow) * Nn + lhalf * 16;
    const __half* gX1 = gX0 + (size_t)64 * Nn;
    const uint32_t sA0 = sbase + lrow * QK_ROWB + lhalf * 32;
    const uint32_t sA1 = sA0 + 64 * QK_ROWB;
    const uint32_t sB0 = sA0 + QK_OPB;
    const uint32_t sB1 = sB0 + 64 * QK_ROWB;

    const uint32_t aoff = (uint32_t)((wm + (lane & 7) + ((lane >> 3) & 1) * 8) * QK_ROWB
                                     + ((lane >> 4) & 1) * 16);
    const uint32_t boff = (uint32_t)((wn + (lane & 7) + ((lane >> 4) & 1) * 8) * QK_ROWB
                                     + ((lane >> 3) & 1) * 16);

#pragma unroll
    for (int s = 0; s < 3; s++) {
        uint32_t st = s * QK_STB;
        int koff = s * 32;
        cp16s(sA0 + st,      gW0 + koff);
        cp16s(sA0 + st + 16, gW0 + koff + 8);
        cp16s(sA1 + st,      gW1 + koff);
        cp16s(sA1 + st + 16, gW1 + koff + 8);
        cp16s(sB0 + st,      gX0 + koff);
        cp16s(sB0 + st + 16, gX0 + koff + 8);
        cp16s(sB1 + st,      gX1 + koff);
        cp16s(sB1 + st + 16, gX1 + koff + 8);
        CP_COMMIT();
    }

    float acc[4][8][4];
#pragma unroll
    for (int i = 0; i < 4; i++)
#pragma unroll
        for (int j = 0; j < 8; j++)
#pragma unroll
            for (int r = 0; r < 4; r++) acc[i][j][r] = 0.f;

    for (int c = 0; c < QK_NCH; c++) {
        CP_WAIT2();
        __syncthreads();
        const uint32_t st = (c & 3) * QK_STB;
        const uint32_t Ab = sbase + st;
        const uint32_t Bbp = Ab + QK_OPB;
#pragma unroll
        for (int ks = 0; ks < 2; ks++) {
            uint32_t af[4][4], bfr[8][2];
#pragma unroll
            for (int mi = 0; mi < 4; mi++)
                LDSM_X4(af[mi][0], af[mi][1], af[mi][2], af[mi][3],
                        Ab + aoff + mi * (16 * QK_ROWB) + ks * 32);
#pragma unroll
            for (int nj = 0; nj < 4; nj++) {
                uint32_t r0, r1, r2, r3;
                LDSM_X4(r0, r1, r2, r3, Bbp + boff + nj * (16 * QK_ROWB) + ks * 32);
                bfr[2 * nj][0] = r0; bfr[2 * nj][1] = r1;
                bfr[2 * nj + 1][0] = r2; bfr[2 * nj + 1][1] = r3;
            }
#pragma unroll
            for (int mi = 0; mi < 4; mi++)
#pragma unroll
                for (int ni = 0; ni < 8; ni++)
                    mma_f16(acc[mi][ni], af[mi], bfr[ni]);
        }
        int nx = c + 3;
        if (nx < QK_NCH) {
            uint32_t s2 = (nx & 3) * QK_STB;
            int koff = nx * 32;
            cp16s(sA0 + s2,      gW0 + koff);
            cp16s(sA0 + s2 + 16, gW0 + koff + 8);
            cp16s(sA1 + s2,      gW1 + koff);
            cp16s(sA1 + s2 + 16, gW1 + koff + 8);
            cp16s(sB0 + s2,      gX0 + koff);
            cp16s(sB0 + s2 + 16, gX0 + koff + 8);
            cp16s(sB1 + s2,      gX1 + koff);
            cp16s(sB1 + s2 + 16, gX1 + koff + 8);
        }
        CP_COMMIT();
        __syncthreads();
    }

    const float* gg  = sel ? gk : gq;
    const float* bbp = sel ? bk : bq;
    const float* mmp = sel ? mk : mq;
    const float* vvp = sel ? vk : vq;
    __half* outp = sel ? g_kh : g_qh;
#pragma unroll
    for (int mi = 0; mi < 4; mi++) {
        int r0 = m0 + wm + mi * 16 + g;
        int r1 = r0 + 8;
        float sc0 = gg[r0] * rsqrtf(vvp[r0] + EPSf);
        float sh0 = bbp[r0] - mmp[r0] * sc0;
        float sc1 = gg[r1] * rsqrtf(vvp[r1] + EPSf);
        float sh1 = bbp[r1] - mmp[r1] * sc1;
#pragma unroll
        for (int ni = 0; ni < 8; ni++) {
            int cn = n0 + wn + ni * 8 + 2 * t4;
            __half2 h0 = __floats2half2_rn(fmaxf(acc[mi][ni][0] * sc0 + sh0, 0.f),
                                           fmaxf(acc[mi][ni][1] * sc0 + sh0, 0.f));
            __half2 h1 = __floats2half2_rn(fmaxf(acc[mi][ni][2] * sc1 + sh1, 0.f),
                                           fmaxf(acc[mi][ni][3] * sc1 + sh1, 0.f));
            *(__half2*)&outp[((size_t)b * N8 + r0) * Cc + cn] = h0;
            *(__half2*)&outp[((size_t)b * N8 + r1) * Cc + cn] = h1;
        }
    }
}

// ---------------------------------------------------------------------------
// sim[b,c,d] -- R10-proven retile: 64x128 block, 128 threads (4 warps 32x64),
// grid 256 CTAs, fp16 mma + trans ldmatrix.
// ---------------------------------------------------------------------------
#define SIM_AROWB 144               // 64 halves + 16B pad
#define SIM_BROWB 272               // 128 halves + 16B pad
#define SIM_APB   (32 * SIM_AROWB)  // 4608
#define SIM_BPB   (32 * SIM_BROWB)  // 8704
#define SIM_STB   (SIM_APB + SIM_BPB)  // 13312
#define SIM_NCH   (N8 / 32)         // 16

__global__ __launch_bounds__(128, 4) void gemm_sim_f16(void) {
    extern __shared__ char rawsm[];
    const uint32_t sbase = smem_u32(rawsm);

    const int b = blockIdx.z;
    const int c0 = blockIdx.y * 64;
    const int d0 = blockIdx.x * 128;
    const int tid = threadIdx.x;
    const int lane = tid & 31, warp = tid >> 5;
    const int wm = (warp >> 1) * 32, wn = (warp & 1) * 64;
    const int g = lane >> 2, t4 = lane & 3;

    const int arow = tid >> 2;
    const int aseg = tid & 3;
    const __half* gK = g_kh + ((size_t)b * N8 + arow) * Cc + c0 + aseg * 8;
    const uint32_t sA = sbase + arow * SIM_AROWB + aseg * 16;
    const int brow = tid >> 4;
    const int bseg = tid & 15;
    const __half* gQ = g_qh + ((size_t)b * N8 + brow) * Cc + d0 + bseg * 8;
    const uint32_t sB = sbase + SIM_APB + brow * SIM_BROWB + bseg * 16;
    const size_t qrow8 = (size_t)8 * Cc;

    const uint32_t aoffT = (uint32_t)(((lane & 7) + ((lane >> 4) & 1) * 8) * SIM_AROWB
                                      + (wm + ((lane >> 3) & 1) * 8) * 2);
    const uint32_t boffT = (uint32_t)(((lane & 7) + ((lane >> 3) & 1) * 8) * SIM_BROWB
                                      + (wn + ((lane >> 4) & 1) * 8) * 2);

#pragma unroll
    for (int s = 0; s < 3; s++) {
        uint32_t st = s * SIM_STB;
        size_t koff = (size_t)s * 32 * Cc;
        cp16s(sA + st,      gK + koff);
        cp16s(sA + st + 64, gK + koff + 32);
#pragma unroll
        for (int j = 0; j < 4; j++)
            cp16s(sB + st + j * (8 * SIM_BROWB), gQ + koff + j * qrow8);
        CP_COMMIT();
    }

    float acc[2][8][4];
#pragma unroll
    for (int i = 0; i < 2; i++)
#pragma unroll
        for (int j = 0; j < 8; j++)
#pragma unroll
            for (int rr = 0; rr < 4; rr++) acc[i][j][rr] = 0.f;

    for (int c = 0; c < SIM_NCH; c++) {
        CP_WAIT2();
        __syncthreads();
        const uint32_t st = (c & 3) * SIM_STB;
        const uint32_t Ab = sbase + st;
        const uint32_t Bbp = sbase + SIM_APB + st;
#pragma unroll
        for (int ks = 0; ks < 2; ks++) {
            uint32_t af[2][4], bfr[8][2];
#pragma unroll
            for (int mi = 0; mi < 2; mi++)
                LDSM_X4_T(af[mi][0], af[mi][1], af[mi][2], af[mi][3],
                          Ab + aoffT + ks * (16 * SIM_AROWB) + mi * 32);
#pragma unroll
            for (int nj = 0; nj < 4; nj++) {
                uint32_t r0, r1, r2, r3;
                LDSM_X4_T(r0, r1, r2, r3,
                          Bbp + boffT + ks * (16 * SIM_BROWB) + nj * 32);
                bfr[2 * nj][0] = r0; bfr[2 * nj][1] = r1;
                bfr[2 * nj + 1][0] = r2; bfr[2 * nj + 1][1] = r3;
            }
#pragma unroll
            for (int mi = 0; mi < 2; mi++)
#pragma unroll
                for (int ni = 0; ni < 8; ni++)
                    mma_f16(acc[mi][ni], af[mi], bfr[ni]);
        }
        int nx = c + 3;
        if (nx < SIM_NCH) {
            uint32_t s2 = (nx & 3) * SIM_STB;
            size_t koff = (size_t)nx * 32 * Cc;
            cp16s(sA + s2,      gK + koff);
            cp16s(sA + s2 + 64, gK + koff + 32);
#pragma unroll
            for (int j = 0; j < 4; j++)
                cp16s(sB + s2 + j * (8 * SIM_BROWB), gQ + koff + j * qrow8);
        }
        CP_COMMIT();
        __syncthreads();
    }

#pragma unroll
    for (int mi = 0; mi < 2; mi++) {
        int r0 = c0 + wm + mi * 16 + g;
        int r1 = r0 + 8;
#pragma unroll
        for (int ni = 0; ni < 8; ni++) {
            int cn = d0 + wn + ni * 8 + 2 * t4;
            float* p0 = g_sim + ((size_t)b * Cc + r0) * Cc + cn;
            float* p1 = g_sim + ((size_t)b * Cc + r1) * Cc + cn;
            *(float2*)p0 = make_float2(acc[mi][ni][0], acc[mi][ni][1]);
            *(float2*)p1 = make_float2(acc[mi][ni][2], acc[mi][ni][3]);
        }
    }
}

// ---------------------------------------------------------------------------
// aff' = alpha * softmax_d(-sim) * s[b,d]  -> fp16 g_simh
// ---------------------------------------------------------------------------
__global__ void softmax_kernel(const float* __restrict__ alpha) {
    int row = blockIdx.x;
    int b = row >> 8;
    const float* p = g_sim + (size_t)row * Cc;
    int t = threadIdx.x;
    float v = -p[t];
    __shared__ float sm[8];
    __shared__ float ss[8];
    float wm = warpMax(v);
    if ((t & 31) == 0) sm[t >> 5] = wm;
    __syncthreads();
    float bm = sm[0];
#pragma unroll
    for (int i = 1; i < 8; i++) bm = fmaxf(bm, sm[i]);
    float e = expf(v - bm);
    float ws = warpSum(e);
    if ((t & 31) == 0) ss[t >> 5] = ws;
    __syncthreads();
    float tot = 0.f;
#pragma unroll
    for (int i = 0; i < 8; i++) tot += ss[i];
    float r = (e / tot) * alpha[0] * g_s[b * Cc + t];
    g_simh[(size_t)row * Cc + t] = __float2half_rn(r);
}

// ---------------------------------------------------------------------------
// out[b,c,n] = sum_d aff'[b,c,d]*x[b,d,n] + x[b,c,n]   (fp16 mma)
// Retiled to R8-proven shape: 128 threads, 4 warps of 64x64.
// ---------------------------------------------------------------------------
#define GO_AROWB 80
#define GO_APB   (128 * GO_AROWB)    // 10240
#define GO_BROWB 272
#define GO_BPB   (32 * GO_BROWB)     // 8704
#define GO_STB   (GO_APB + GO_BPB)   // 18944
#define GO_NCH   (Cc / 32)           // 8

__global__ __launch_bounds__(128, 2) void gemm_out_f16(
    const float* __restrict__ x, float* __restrict__ out) {
    extern __shared__ char rawsm[];
    const uint32_t sbase = smem_u32(rawsm);

    const int b = blockIdx.z;
    const int m0 = blockIdx.y * 128;
    const int n0 = blockIdx.x * 128;
    const int tid = threadIdx.x;
    const int lane = tid & 31, warp = tid >> 5;
    const int wm = (warp >> 1) * 64, wn = (warp & 1) * 64;
    const int g = lane >> 2, t4 = lane & 3;

    // A loader: thread tid owns row (m0+tid); loads its 64B chunk as 4x16B.
    const __half* gA = g_simh + ((size_t)b * Cc + m0 + tid) * Cc;
    const uint32_t sA = sbase + tid * GO_AROWB;
    // B loader: brow = tid>>4 (0..7), bseg = tid&15; rows +0,8,16,24.
    const int brow = tid >> 4;
    const int bseg = tid & 15;
    const __half* gB = g_xh + ((size_t)b * Cc + brow) * Nn + n0 + bseg * 8;
    const uint32_t sB = sbase + GO_APB + brow * GO_BROWB + bseg * 16;
    const size_t brow8 = (size_t)8 * Nn;

    const uint32_t aoff = (uint32_t)((wm + (lane & 7) + ((lane >> 3) & 1) * 8) * GO_AROWB
                                     + ((lane >> 4) & 1) * 16);
    const uint32_t boffT = (uint32_t)(((lane & 7) + ((lane >> 3) & 1) * 8) * GO_BROWB
                                      + (wn + ((lane >> 4) & 1) * 8) * 2);

#pragma unroll
    for (int s = 0; s < 3; s++) {
        uint32_t st = s * GO_STB;
        int koff = s * 32;
#pragma unroll
        for (int j = 0; j < 4; j++)
            cp16s(sA + st + j * 16, gA + koff + j * 8);
        size_t bk = (size_t)s * 32 * Nn;
#pragma unroll
        for (int j = 0; j < 4; j++)
            cp16s(sB + st + j * (8 * GO_BROWB), gB + bk + j * brow8);
        CP_COMMIT();
    }

    float acc[4][8][4];
#pragma unroll
    for (int i = 0; i < 4; i++)
#pragma unroll
        for (int j = 0; j < 8; j++)
#pragma unroll
            for (int rr = 0; rr < 4; rr++) acc[i][j][rr] = 0.f;

    for (int c = 0; c < GO_NCH; c++) {
        CP_WAIT2();
        __syncthreads();
        const uint32_t st = (c & 3) * GO_STB;
        const uint32_t Ab = sbase + st;
        const uint32_t Bbp = sbase + GO_APB + st;
#pragma unroll
        for (int ks = 0; ks < 2; ks++) {
            uint32_t af[4][4], bfr[8][2];
#pragma unroll
            for (int mi = 0; mi < 4; mi++)
                LDSM_X4(af[mi][0], af[mi][1], af[mi][2], af[mi][3],
                        Ab + aoff + mi * (16 * GO_AROWB) + ks * 32);
#pragma unroll
            for (int nj = 0; nj < 4; nj++) {
                uint32_t r0, r1, r2, r3;
                LDSM_X4_T(r0, r1, r2, r3,
                          Bbp + boffT + ks * (16 * GO_BROWB) + nj * 32);
                bfr[2 * nj][0] = r0; bfr[2 * nj][1] = r1;
                bfr[2 * nj + 1][0] = r2; bfr[2 * nj + 1][1] = r3;
            }
#pragma unroll
            for (int mi = 0; mi < 4; mi++)
#pragma unroll
                for (int ni = 0; ni < 8; ni++)
                    mma_f16(acc[mi][ni], af[mi], bfr[ni]);
        }
        int nx = c + 3;
        if (nx < GO_NCH) {
            uint32_t s2 = (nx & 3) * GO_STB;
            int koff = nx * 32;
#pragma unroll
            for (int j = 0; j < 4; j++)
                cp16s(sA + s2 + j * 16, gA + koff + j * 8);
            size_t bk = (size_t)nx * 32 * Nn;
#pragma unroll
            for (int j = 0; j < 4; j++)
                cp16s(sB + s2 + j * (8 * GO_BROWB), gB + bk + j * brow8);
        }
        CP_COMMIT();
        __syncthreads();
    }

#pragma unroll
    for (int mi = 0; mi < 4; mi++) {
        int r0 = m0 + wm + mi * 16 + g;
        int r1 = r0 + 8;
#pragma unroll
        for (int ni = 0; ni < 8; ni++) {
            int cn = n0 + wn + ni * 8 + 2 * t4;
            size_t a0 = ((size_t)b * Cc + r0) * Nn + cn;
            size_t a1 = ((size_t)b * Cc + r1) * Nn + cn;
            float2 x0 = *(const float2*)(x + a0);
            float2 x1 = *(const float2*)(x + a1);
            *(float2*)(out + a0) = make_float2(acc[mi][ni][0] + x0.x, acc[mi][ni][1] + x0.y);
            *(float2*)(out + a1) = make_float2(acc[mi][ni][2] + x1.x, acc[mi][ni][3] + x1.y);
        }
    }
}

// ---------------------------------------------------------------------------
extern "C" void kernel_launch(void* const* d_in, const int* in_sizes, int n_in,
                              void* d_out, int out_size) {
    const float* x    = (const float*)d_in[0];
    const float* Wq   = (const float*)d_in[1];
    const float* bn1g = (const float*)d_in[2];
    const float* bn1b = (const float*)d_in[3];
    const float* bn1m = (const float*)d_in[4];
    const float* bn1v = (const float*)d_in[5];
    const float* Wk   = (const float*)d_in[6];
    const float* bn2g = (const float*)d_in[7];
    const float* bn2b = (const float*)d_in[8];
    const float* bn2m = (const float*)d_in[9];
    const float* bn2v = (const float*)d_in[10];
    const float* W1   = (const float*)d_in[11];
    const float* W2   = (const float*)d_in[12];
    const float* alpha = (const float*)d_in[13];
    float* out = (float*)d_out;

    const int qk_smem  = 4 * QK_STB;    // 81920 B
    const int sim_smem = 4 * SIM_STB;   // 53248 B
    const int go_smem  = 4 * GO_STB;    // 75776 B
    cudaFuncSetAttribute(gemm_qk_f16,  cudaFuncAttributeMaxDynamicSharedMemorySize, qk_smem);
    cudaFuncSetAttribute(gemm_sim_f16, cudaFuncAttributeMaxDynamicSharedMemorySize, sim_smem);
    cudaFuncSetAttribute(gemm_out_f16, cudaFuncAttributeMaxDynamicSharedMemorySize, go_smem);

    prep_kernel<<<POOL_BLOCKS + CONVW_BLOCKS, 256>>>(x, Wq, Wk);
    se_kernel<<<Bb, 256>>>(W1, W2);

    dim3 g1(Cc / 128, N8 / 128, 2 * Bb);
    gemm_qk_f16<<<g1, 128, qk_smem>>>(bn1g, bn1b, bn1m, bn1v,
                                      bn2g, bn2b, bn2m, bn2v);

    dim3 g2(Cc / 128, Cc / 64, Bb);
    gemm_sim_f16<<<g2, 128, sim_smem>>>();

    softmax_kernel<<<Bb * Cc, 256>>>(alpha);

    dim3 g3(Nn / 128, Cc / 128, Bb);
    gemm_out_f16<<<g3, 128, go_smem>>>(x, out);
}

// round 13
// speedup vs baseline: 1.0282x; 1.0282x over previous
#include <cuda_runtime.h>
#include <cuda_fp16.h>
#include <cstdint>

#define Bb 32
#define Cc 256
#define Nn 4096
#define N8 512
#define EPSf 1e-5f

// Scratch (device globals — no allocation allowed)
__device__ __half g_qh[(size_t)Bb * N8 * Cc];   // fp16 q (BN+ReLU output)
__device__ __half g_kh[(size_t)Bb * N8 * Cc];   // fp16 k
__device__ float  g_sim[(size_t)Bb * Cc * Cc];  // fp32 sim
__device__ __half g_simh[(size_t)Bb * Cc * Cc]; // fp16 alpha*aff*s
__device__ float  g_pooled[Bb * Cc];
__device__ float  g_s[Bb * Cc];
__device__ __half g_xh[(size_t)Bb * Cc * Nn];   // fp16 copy of x
__device__ __half g_Wqh[(size_t)N8 * Nn];
__device__ __half g_Wkh[(size_t)N8 * Nn];

__device__ __forceinline__ float warpMax(float v) {
#pragma unroll
    for (int o = 16; o; o >>= 1) v = fmaxf(v, __shfl_xor_sync(0xffffffffu, v, o));
    return v;
}
__device__ __forceinline__ float warpSum(float v) {
#pragma unroll
    for (int o = 16; o; o >>= 1) v += __shfl_xor_sync(0xffffffffu, v, o);
    return v;
}

__device__ __forceinline__ void mma_f16(float* c, const uint32_t* a, const uint32_t* b) {
    asm volatile(
        "mma.sync.aligned.m16n8k16.row.col.f32.f16.f16.f32 "
        "{%0,%1,%2,%3}, {%4,%5,%6,%7}, {%8,%9}, {%0,%1,%2,%3};\n"
        : "+f"(c[0]), "+f"(c[1]), "+f"(c[2]), "+f"(c[3])
        : "r"(a[0]), "r"(a[1]), "r"(a[2]), "r"(a[3]), "r"(b[0]), "r"(b[1]));
}
#define LDSM_X4(r0, r1, r2, r3, addr) \
    asm volatile("ldmatrix.sync.aligned.m8n8.x4.shared.b16 {%0,%1,%2,%3}, [%4];" \
                 : "=r"(r0), "=r"(r1), "=r"(r2), "=r"(r3) : "r"(addr))
#define LDSM_X4_T(r0, r1, r2, r3, addr) \
    asm volatile("ldmatrix.sync.aligned.m8n8.x4.trans.shared.b16 {%0,%1,%2,%3}, [%4];" \
                 : "=r"(r0), "=r"(r1), "=r"(r2), "=r"(r3) : "r"(addr))

__device__ __forceinline__ void cp16s(uint32_t saddr, const void* g) {
    asm volatile("cp.async.cg.shared.global [%0], [%1], 16;" :: "r"(saddr), "l"(g));
}
#define CP_COMMIT() asm volatile("cp.async.commit_group;")
#define CP_WAIT2()  asm volatile("cp.async.wait_group 2;")

__device__ __forceinline__ uint32_t smem_u32(const void* p) {
    return (uint32_t)__cvta_generic_to_shared(p);
}

// ---------------------------------------------------------------------------
// Fused prep: blocks [0, Bb*Cc) do pool+x->fp16; the rest convert Wq/Wk.
// ---------------------------------------------------------------------------
#define POOL_BLOCKS (Bb * Cc)
#define CONVW_BLOCKS ((N8 * Nn / 4) / 256)

__global__ void prep_kernel(const float* __restrict__ x,
                            const float* __restrict__ Wq,
                            const float* __restrict__ Wk) {
    if (blockIdx.x < POOL_BLOCKS) {
        int row = blockIdx.x;  // b*Cc + c
        const float4* xr = (const float4*)(x + (size_t)row * Nn);
        uint2* xh = (uint2*)(g_xh + (size_t)row * Nn);
        float m = -3.0e38f;
        for (int i = threadIdx.x; i < Nn / 4; i += 256) {
            float4 v = xr[i];
            __half2 p01 = __floats2half2_rn(v.x, v.y);
            __half2 p23 = __floats2half2_rn(v.z, v.w);
            uint2 u;
            u.x = *reinterpret_cast<uint32_t*>(&p01);
            u.y = *reinterpret_cast<uint32_t*>(&p23);
            xh[i] = u;
            m = fmaxf(m, fmaxf(fmaxf(v.x, v.y), fmaxf(v.z, v.w)));
        }
        m = warpMax(m);
        __shared__ float sm[8];
        if ((threadIdx.x & 31) == 0) sm[threadIdx.x >> 5] = m;
        __syncthreads();
        if (threadIdx.x == 0) {
            float r = sm[0];
#pragma unroll
            for (int i = 1; i < 8; i++) r = fmaxf(r, sm[i]);
            g_pooled[row] = r;
        }
    } else {
        int i = (blockIdx.x - POOL_BLOCKS) * 256 + threadIdx.x;
        float4 q = ((const float4*)Wq)[i];
        float4 k = ((const float4*)Wk)[i];
        __half2 q01 = __floats2half2_rn(q.x, q.y), q23 = __floats2half2_rn(q.z, q.w);
        __half2 k01 = __floats2half2_rn(k.x, k.y), k23 = __floats2half2_rn(k.z, k.w);
        uint2 uq, uk;
        uq.x = *reinterpret_cast<uint32_t*>(&q01); uq.y = *reinterpret_cast<uint32_t*>(&q23);
        uk.x = *reinterpret_cast<uint32_t*>(&k01); uk.y = *reinterpret_cast<uint32_t*>(&k23);
        ((uint2*)g_Wqh)[i] = uq;
        ((uint2*)g_Wkh)[i] = uk;
    }
}

// ---------------------------------------------------------------------------
__global__ void se_kernel(const float* __restrict__ W1, const float* __restrict__ W2) {
    int b = blockIdx.x;
    int t = threadIdx.x;
    __shared__ float h[32];
    if (t < 32) {
        float acc = 0.f;
        const float* w = W1 + t * Cc;
        const float* p = g_pooled + b * Cc;
        for (int c = 0; c < Cc; c++) acc += w[c] * p[c];
        h[t] = fmaxf(acc, 0.f);
    }
    __syncthreads();
    float acc = 0.f;
    const float* w2 = W2 + t * 32;
#pragma unroll
    for (int j = 0; j < 32; j++) acc += w2[j] * h[j];
    g_s[b * Cc + t] = 1.f / (1.f + expf(-acc));
}

// ---------------------------------------------------------------------------
// fp16 q/k GEMM: R8-proven config. Block 128x128, 4 warps of 64x64, kc=32,
// 4-stage cp.async, wait_group 2, LDSM/MMA first, prefetch after, two barriers.
// ---------------------------------------------------------------------------
#define QK_ROWB 80
#define QK_OPB  10240       // 128 rows * 80 B
#define QK_STB  20480
#define QK_NCH  (Nn / 32)   // 128

__global__ __launch_bounds__(128, 2) void gemm_qk_f16(
    const float* __restrict__ gq, const float* __restrict__ bq,
    const float* __restrict__ mq, const float* __restrict__ vq,
    const float* __restrict__ gk, const float* __restrict__ bk,
    const float* __restrict__ mk, const float* __restrict__ vk) {
    extern __shared__ char rawsm[];
    const uint32_t sbase = smem_u32(rawsm);

    const int z = blockIdx.z;
    const int b = z >> 1;
    const int sel = z & 1;
    const int m0 = blockIdx.y * 128;
    const int n0 = blockIdx.x * 128;
    const int tid = threadIdx.x;
    const int lane = tid & 31, warp = tid >> 5;
    const int wm = (warp >> 1) * 64, wn = (warp & 1) * 64;
    const int g = lane >> 2, t4 = lane & 3;

    const int lrow = tid >> 1;
    const int lhalf = tid & 1;
    const __half* gW0 = (sel ? g_Wkh : g_Wqh) + (size_t)(m0 + lrow) * Nn + lhalf * 16;
    const __half* gW1 = gW0 + (size_t)64 * Nn;
    const __half* gX0 = g_xh + ((size_t)b * Cc + n0 + lrow) * Nn + lhalf * 16;
    const __half* gX1 = gX0 + (size_t)64 * Nn;
    const uint32_t sA0 = sbase + lrow * QK_ROWB + lhalf * 32;
    const uint32_t sA1 = sA0 + 64 * QK_ROWB;
    const uint32_t sB0 = sA0 + QK_OPB;
    const uint32_t sB1 = sB0 + 64 * QK_ROWB;

    const uint32_t aoff = (uint32_t)((wm + (lane & 7) + ((lane >> 3) & 1) * 8) * QK_ROWB
                                     + ((lane >> 4) & 1) * 16);
    const uint32_t boff = (uint32_t)((wn + (lane & 7) + ((lane >> 4) & 1) * 8) * QK_ROWB
                                     + ((lane >> 3) & 1) * 16);

#pragma unroll
    for (int s = 0; s < 3; s++) {
        uint32_t st = s * QK_STB;
        int koff = s * 32;
        cp16s(sA0 + st,      gW0 + koff);
        cp16s(sA0 + st + 16, gW0 + koff + 8);
        cp16s(sA1 + st,      gW1 + koff);
        cp16s(sA1 + st + 16, gW1 + koff + 8);
        cp16s(sB0 + st,      gX0 + koff);
        cp16s(sB0 + st + 16, gX0 + koff + 8);
        cp16s(sB1 + st,      gX1 + koff);
        cp16s(sB1 + st + 16, gX1 + koff + 8);
        CP_COMMIT();
    }

    float acc[4][8][4];
#pragma unroll
    for (int i = 0; i < 4; i++)
#pragma unroll
        for (int j = 0; j < 8; j++)
#pragma unroll
            for (int r = 0; r < 4; r++) acc[i][j][r] = 0.f;

    for (int c = 0; c < QK_NCH; c++) {
        CP_WAIT2();
        __syncthreads();
        const uint32_t st = (c & 3) * QK_STB;
        const uint32_t Ab = sbase + st;
        const uint32_t Bbp = Ab + QK_OPB;
#pragma unroll
        for (int ks = 0; ks < 2; ks++) {
            uint32_t af[4][4], bfr[8][2];
#pragma unroll
            for (int mi = 0; mi < 4; mi++)
                LDSM_X4(af[mi][0], af[mi][1], af[mi][2], af[mi][3],
                        Ab + aoff + mi * (16 * QK_ROWB) + ks * 32);
#pragma unroll
            for (int nj = 0; nj < 4; nj++) {
                uint32_t r0, r1, r2, r3;
                LDSM_X4(r0, r1, r2, r3, Bbp + boff + nj * (16 * QK_ROWB) + ks * 32);
                bfr[2 * nj][0] = r0; bfr[2 * nj][1] = r1;
                bfr[2 * nj + 1][0] = r2; bfr[2 * nj + 1][1] = r3;
            }
#pragma unroll
            for (int mi = 0; mi < 4; mi++)
#pragma unroll
                for (int ni = 0; ni < 8; ni++)
                    mma_f16(acc[mi][ni], af[mi], bfr[ni]);
        }
        int nx = c + 3;
        if (nx < QK_NCH) {
            uint32_t s2 = (nx & 3) * QK_STB;
            int koff = nx * 32;
            cp16s(sA0 + s2,      gW0 + koff);
            cp16s(sA0 + s2 + 16, gW0 + koff + 8);
            cp16s(sA1 + s2,      gW1 + koff);
            cp16s(sA1 + s2 + 16, gW1 + koff + 8);
            cp16s(sB0 + s2,      gX0 + koff);
            cp16s(sB0 + s2 + 16, gX0 + koff + 8);
            cp16s(sB1 + s2,      gX1 + koff);
            cp16s(sB1 + s2 + 16, gX1 + koff + 8);
        }
        CP_COMMIT();
        __syncthreads();
    }

    const float* gg  = sel ? gk : gq;
    const float* bbp = sel ? bk : bq;
    const float* mmp = sel ? mk : mq;
    const float* vvp = sel ? vk : vq;
    __half* outp = sel ? g_kh : g_qh;
#pragma unroll
    for (int mi = 0; mi < 4; mi++) {
        int r0 = m0 + wm + mi * 16 + g;
        int r1 = r0 + 8;
        float sc0 = gg[r0] * rsqrtf(vvp[r0] + EPSf);
        float sh0 = bbp[r0] - mmp[r0] * sc0;
        float sc1 = gg[r1] * rsqrtf(vvp[r1] + EPSf);
        float sh1 = bbp[r1] - mmp[r1] * sc1;
#pragma unroll
        for (int ni = 0; ni < 8; ni++) {
            int cn = n0 + wn + ni * 8 + 2 * t4;
            __half2 h0 = __floats2half2_rn(fmaxf(acc[mi][ni][0] * sc0 + sh0, 0.f),
                                           fmaxf(acc[mi][ni][1] * sc0 + sh0, 0.f));
            __half2 h1 = __floats2half2_rn(fmaxf(acc[mi][ni][2] * sc1 + sh1, 0.f),
                                           fmaxf(acc[mi][ni][3] * sc1 + sh1, 0.f));
            *(__half2*)&outp[((size_t)b * N8 + r0) * Cc + cn] = h0;
            *(__half2*)&outp[((size_t)b * N8 + r1) * Cc + cn] = h1;
        }
    }
}

// ---------------------------------------------------------------------------
// sim[b,c,d] -- R10-proven retile: 64x128 block, 128 threads (4 warps 32x64),
// grid 256 CTAs, fp16 mma + trans ldmatrix.
// ---------------------------------------------------------------------------
#define SIM_AROWB 144               // 64 halves + 16B pad
#define SIM_BROWB 272               // 128 halves + 16B pad
#define SIM_APB   (32 * SIM_AROWB)  // 4608
#define SIM_BPB   (32 * SIM_BROWB)  // 8704
#define SIM_STB   (SIM_APB + SIM_BPB)  // 13312
#define SIM_NCH   (N8 / 32)         // 16

__global__ __launch_bounds__(128, 4) void gemm_sim_f16(void) {
    extern __shared__ char rawsm[];
    const uint32_t sbase = smem_u32(rawsm);

    const int b = blockIdx.z;
    const int c0 = blockIdx.y * 64;
    const int d0 = blockIdx.x * 128;
    const int tid = threadIdx.x;
    const int lane = tid & 31, warp = tid >> 5;
    const int wm = (warp >> 1) * 32, wn = (warp & 1) * 64;
    const int g = lane >> 2, t4 = lane & 3;

    const int arow = tid >> 2;
    const int aseg = tid & 3;
    const __half* gK = g_kh + ((size_t)b * N8 + arow) * Cc + c0 + aseg * 8;
    const uint32_t sA = sbase + arow * SIM_AROWB + aseg * 16;
    const int brow = tid >> 4;
    const int bseg = tid & 15;
    const __half* gQ = g_qh + ((size_t)b * N8 + brow) * Cc + d0 + bseg * 8;
    const uint32_t sB = sbase + SIM_APB + brow * SIM_BROWB + bseg * 16;
    const size_t qrow8 = (size_t)8 * Cc;

    const uint32_t aoffT = (uint32_t)(((lane & 7) + ((lane >> 4) & 1) * 8) * SIM_AROWB
                                      + (wm + ((lane >> 3) & 1) * 8) * 2);
    const uint32_t boffT = (uint32_t)(((lane & 7) + ((lane >> 3) & 1) * 8) * SIM_BROWB
                                      + (wn + ((lane >> 4) & 1) * 8) * 2);

#pragma unroll
    for (int s = 0; s < 3; s++) {
        uint32_t st = s * SIM_STB;
        size_t koff = (size_t)s * 32 * Cc;
        cp16s(sA + st,      gK + koff);
        cp16s(sA + st + 64, gK + koff + 32);
#pragma unroll
        for (int j = 0; j < 4; j++)
            cp16s(sB + st + j * (8 * SIM_BROWB), gQ + koff + j * qrow8);
        CP_COMMIT();
    }

    float acc[2][8][4];
#pragma unroll
    for (int i = 0; i < 2; i++)
#pragma unroll
        for (int j = 0; j < 8; j++)
#pragma unroll
            for (int rr = 0; rr < 4; rr++) acc[i][j][rr] = 0.f;

    for (int c = 0; c < SIM_NCH; c++) {
        CP_WAIT2();
        __syncthreads();
        const uint32_t st = (c & 3) * SIM_STB;
        const uint32_t Ab = sbase + st;
        const uint32_t Bbp = sbase + SIM_APB + st;
#pragma unroll
        for (int ks = 0; ks < 2; ks++) {
            uint32_t af[2][4], bfr[8][2];
#pragma unroll
            for (int mi = 0; mi < 2; mi++)
                LDSM_X4_T(af[mi][0], af[mi][1], af[mi][2], af[mi][3],
                          Ab + aoffT + ks * (16 * SIM_AROWB) + mi * 32);
#pragma unroll
            for (int nj = 0; nj < 4; nj++) {
                uint32_t r0, r1, r2, r3;
                LDSM_X4_T(r0, r1, r2, r3,
                          Bbp + boffT + ks * (16 * SIM_BROWB) + nj * 32);
                bfr[2 * nj][0] = r0; bfr[2 * nj][1] = r1;
                bfr[2 * nj + 1][0] = r2; bfr[2 * nj + 1][1] = r3;
            }
#pragma unroll
            for (int mi = 0; mi < 2; mi++)
#pragma unroll
                for (int ni = 0; ni < 8; ni++)
                    mma_f16(acc[mi][ni], af[mi], bfr[ni]);
        }
        int nx = c + 3;
        if (nx < SIM_NCH) {
            uint32_t s2 = (nx & 3) * SIM_STB;
            size_t koff = (size_t)nx * 32 * Cc;
            cp16s(sA + s2,      gK + koff);
            cp16s(sA + s2 + 64, gK + koff + 32);
#pragma unroll
            for (int j = 0; j < 4; j++)
                cp16s(sB + s2 + j * (8 * SIM_BROWB), gQ + koff + j * qrow8);
        }
        CP_COMMIT();
        __syncthreads();
    }

#pragma unroll
    for (int mi = 0; mi < 2; mi++) {
        int r0 = c0 + wm + mi * 16 + g;
        int r1 = r0 + 8;
#pragma unroll
        for (int ni = 0; ni < 8; ni++) {
            int cn = d0 + wn + ni * 8 + 2 * t4;
            float* p0 = g_sim + ((size_t)b * Cc + r0) * Cc + cn;
            float* p1 = g_sim + ((size_t)b * Cc + r1) * Cc + cn;
            *(float2*)p0 = make_float2(acc[mi][ni][0], acc[mi][ni][1]);
            *(float2*)p1 = make_float2(acc[mi][ni][2], acc[mi][ni][3]);
        }
    }
}

// ---------------------------------------------------------------------------
// aff' = alpha * softmax_d(-sim) * s[b,d]  -> fp16 g_simh
// ---------------------------------------------------------------------------
__global__ void softmax_kernel(const float* __restrict__ alpha) {
    int row = blockIdx.x;
    int b = row >> 8;
    const float* p = g_sim + (size_t)row * Cc;
    int t = threadIdx.x;
    float v = -p[t];
    __shared__ float sm[8];
    __shared__ float ss[8];
    float wm = warpMax(v);
    if ((t & 31) == 0) sm[t >> 5] = wm;
    __syncthreads();
    float bm = sm[0];
#pragma unroll
    for (int i = 1; i < 8; i++) bm = fmaxf(bm, sm[i]);
    float e = expf(v - bm);
    float ws = warpSum(e);
    if ((t & 31) == 0) ss[t >> 5] = ws;
    __syncthreads();
    float tot = 0.f;
#pragma unroll
    for (int i = 0; i < 8; i++) tot += ss[i];
    float r = (e / tot) * alpha[0] * g_s[b * Cc + t];
    g_simh[(size_t)row * Cc + t] = __float2half_rn(r);
}

// ---------------------------------------------------------------------------
// out[b,c,n] = sum_d aff'[b,c,d]*x[b,d,n] + x[b,c,n]   (fp16 mma)
// R11-proven shape (256 thr, 8 warps 64x32); residual read from g_xh (fp16).
// ---------------------------------------------------------------------------
#define GO_AROWB 80
#define GO_APB   (128 * GO_AROWB)
#define GO_BROWB 272
#define GO_BPB   (32 * GO_BROWB)
#define GO_STB   (GO_APB + GO_BPB)
#define GO_NCH   (Cc / 32)

__global__ __launch_bounds__(256, 2) void gemm_out_f16(
    const float* __restrict__ x, float* __restrict__ out) {
    extern __shared__ char rawsm[];
    const uint32_t sbase = smem_u32(rawsm);

    const int b = blockIdx.z;
    const int m0 = blockIdx.y * 128;
    const int n0 = blockIdx.x * 128;
    const int tid = threadIdx.x;
    const int lane = tid & 31, warp = tid >> 5;
    const int wm = (warp >> 2) * 64, wn = (warp & 3) * 32;
    const int g = lane >> 2, t4 = lane & 3;

    const int arow = tid >> 1;
    const int apart = tid & 1;
    const __half* gA = g_simh + ((size_t)b * Cc + m0 + arow) * Cc + apart * 16;
    const uint32_t sA = sbase + arow * GO_AROWB + apart * 32;
    const int brow = tid >> 4;
    const int bseg = tid & 15;
    const __half* gB = g_xh + ((size_t)b * Cc + brow) * Nn + n0 + bseg * 8;
    const uint32_t sB = sbase + GO_APB + brow * GO_BROWB + bseg * 16;
    const size_t brstep16 = (size_t)16 * Nn;

    const uint32_t aoff = (uint32_t)((wm + (lane & 7) + ((lane >> 3) & 1) * 8) * GO_AROWB
                                     + ((lane >> 4) & 1) * 16);
    const uint32_t boffT = (uint32_t)(((lane & 7) + ((lane >> 3) & 1) * 8) * GO_BROWB
                                      + (wn + ((lane >> 4) & 1) * 8) * 2);

#pragma unroll
    for (int s = 0; s < 3; s++) {
        uint32_t st = s * GO_STB;
        cp16s(sA + st,      gA + s * 32);
        cp16s(sA + st + 16, gA + s * 32 + 8);
        size_t bk = (size_t)s * 32 * Nn;
        cp16s(sB + st, gB + bk);
        cp16s(sB + st + 16 * GO_BROWB, gB + bk + brstep16);
        CP_COMMIT();
    }

    float acc[4][4][4];
#pragma unroll
    for (int i = 0; i < 4; i++)
#pragma unroll
        for (int j = 0; j < 4; j++)
#pragma unroll
            for (int rr = 0; rr < 4; rr++) acc[i][j][rr] = 0.f;

    for (int c = 0; c < GO_NCH; c++) {
        CP_WAIT2();
        __syncthreads();
        const uint32_t st = (c & 3) * GO_STB;
        const uint32_t Ab = sbase + st;
        const uint32_t Bbp = sbase + GO_APB + st;
#pragma unroll
        for (int ks = 0; ks < 2; ks++) {
            uint32_t af[4][4], bfr[4][2];
#pragma unroll
            for (int mi = 0; mi < 4; mi++)
                LDSM_X4(af[mi][0], af[mi][1], af[mi][2], af[mi][3],
                        Ab + aoff + mi * (16 * GO_AROWB) + ks * 32);
#pragma unroll
            for (int nj = 0; nj < 2; nj++) {
                uint32_t r0, r1, r2, r3;
                LDSM_X4_T(r0, r1, r2, r3,
                          Bbp + boffT + ks * (16 * GO_BROWB) + nj * 32);
                bfr[2 * nj][0] = r0; bfr[2 * nj][1] = r1;
                bfr[2 * nj + 1][0] = r2; bfr[2 * nj + 1][1] = r3;
            }
#pragma unroll
            for (int mi = 0; mi < 4; mi++)
#pragma unroll
                for (int ni = 0; ni < 4; ni++)
                    mma_f16(acc[mi][ni], af[mi], bfr[ni]);
        }
        int nx = c + 3;
        if (nx < GO_NCH) {
            uint32_t s2 = (nx & 3) * GO_STB;
            cp16s(sA + s2,      gA + nx * 32);
            cp16s(sA + s2 + 16, gA + nx * 32 + 8);
            size_t bk = (size_t)nx * 32 * Nn;
            cp16s(sB + s2, gB + bk);
            cp16s(sB + s2 + 16 * GO_BROWB, gB + bk + brstep16);
        }
        CP_COMMIT();
        __syncthreads();
    }

#pragma unroll
    for (int mi = 0; mi < 4; mi++) {
        int r0 = m0 + wm + mi * 16 + g;
        int r1 = r0 + 8;
#pragma unroll
        for (int ni = 0; ni < 4; ni++) {
            int cn = n0 + wn + ni * 8 + 2 * t4;
            size_t a0 = ((size_t)b * Cc + r0) * Nn + cn;
            size_t a1 = ((size_t)b * Cc + r1) * Nn + cn;
            // residual from fp16 x copy (halves DRAM read; warm in L2 from B loads)
            float2 x0 = __half22float2(*(const __half2*)(g_xh + a0));
            float2 x1 = __half22float2(*(const __half2*)(g_xh + a1));
            *(float2*)(out + a0) = make_float2(acc[mi][ni][0] + x0.x, acc[mi][ni][1] + x0.y);
            *(float2*)(out + a1) = make_float2(acc[mi][ni][2] + x1.x, acc[mi][ni][3] + x1.y);
        }
    }
}

// ---------------------------------------------------------------------------
extern "C" void kernel_launch(void* const* d_in, const int* in_sizes, int n_in,
                              void* d_out, int out_size) {
    const float* x    = (const float*)d_in[0];
    const float* Wq   = (const float*)d_in[1];
    const float* bn1g = (const float*)d_in[2];
    const float* bn1b = (const float*)d_in[3];
    const float* bn1m = (const float*)d_in[4];
    const float* bn1v = (const float*)d_in[5];
    const float* Wk   = (const float*)d_in[6];
    const float* bn2g = (const float*)d_in[7];
    const float* bn2b = (const float*)d_in[8];
    const float* bn2m = (const float*)d_in[9];
    const float* bn2v = (const float*)d_in[10];
    const float* W1   = (const float*)d_in[11];
    const float* W2   = (const float*)d_in[12];
    const float* alpha = (const float*)d_in[13];
    float* out = (float*)d_out;

    const int qk_smem  = 4 * QK_STB;    // 81920 B
    const int sim_smem = 4 * SIM_STB;   // 53248 B
    const int go_smem  = 4 * GO_STB;    // 75776 B
    cudaFuncSetAttribute(gemm_qk_f16,  cudaFuncAttributeMaxDynamicSharedMemorySize, qk_smem);
    cudaFuncSetAttribute(gemm_sim_f16, cudaFuncAttributeMaxDynamicSharedMemorySize, sim_smem);
    cudaFuncSetAttribute(gemm_out_f16, cudaFuncAttributeMaxDynamicSharedMemorySize, go_smem);

    prep_kernel<<<POOL_BLOCKS + CONVW_BLOCKS, 256>>>(x, Wq, Wk);
    se_kernel<<<Bb, 256>>>(W1, W2);

    dim3 g1(Cc / 128, N8 / 128, 2 * Bb);
    gemm_qk_f16<<<g1, 128, qk_smem>>>(bn1g, bn1b, bn1m, bn1v,
                                      bn2g, bn2b, bn2m, bn2v);

    dim3 g2(Cc / 128, Cc / 64, Bb);
    gemm_sim_f16<<<g2, 128, sim_smem>>>();

    softmax_kernel<<<Bb * Cc, 256>>>(alpha);

    dim3 g3(Nn / 128, Cc / 128, Bb);
    gemm_out_f16<<<g3, 256, go_smem>>>(x, out);
}

// round 14
// speedup vs baseline: 1.0586x; 1.0295x over previous
#include <cuda_runtime.h>
#include <cuda_fp16.h>
#include <cstdint>

#define Bb 32
#define Cc 256
#define Nn 4096
#define N8 512
#define EPSf 1e-5f

// Scratch (device globals — no allocation allowed)
__device__ __half g_qh[(size_t)Bb * N8 * Cc];   // fp16 q (BN+ReLU output)
__device__ __half g_kh[(size_t)Bb * N8 * Cc];   // fp16 k
__device__ float  g_sim[(size_t)Bb * Cc * Cc];  // fp32 sim
__device__ __half g_simh[(size_t)Bb * Cc * Cc]; // fp16 alpha*aff*s
__device__ float  g_pooled[Bb * Cc];
__device__ float  g_s[Bb * Cc];
__device__ __half g_xh[(size_t)Bb * Cc * Nn];   // fp16 copy of x
__device__ __half g_Wqh[(size_t)N8 * Nn];
__device__ __half g_Wkh[(size_t)N8 * Nn];

__device__ __forceinline__ float warpMax(float v) {
#pragma unroll
    for (int o = 16; o; o >>= 1) v = fmaxf(v, __shfl_xor_sync(0xffffffffu, v, o));
    return v;
}
__device__ __forceinline__ float warpSum(float v) {
#pragma unroll
    for (int o = 16; o; o >>= 1) v += __shfl_xor_sync(0xffffffffu, v, o);
    return v;
}

__device__ __forceinline__ void mma_f16(float* c, const uint32_t* a, const uint32_t* b) {
    asm volatile(
        "mma.sync.aligned.m16n8k16.row.col.f32.f16.f16.f32 "
        "{%0,%1,%2,%3}, {%4,%5,%6,%7}, {%8,%9}, {%0,%1,%2,%3};\n"
        : "+f"(c[0]), "+f"(c[1]), "+f"(c[2]), "+f"(c[3])
        : "r"(a[0]), "r"(a[1]), "r"(a[2]), "r"(a[3]), "r"(b[0]), "r"(b[1]));
}
#define LDSM_X4(r0, r1, r2, r3, addr) \
    asm volatile("ldmatrix.sync.aligned.m8n8.x4.shared.b16 {%0,%1,%2,%3}, [%4];" \
                 : "=r"(r0), "=r"(r1), "=r"(r2), "=r"(r3) : "r"(addr))
#define LDSM_X4_T(r0, r1, r2, r3, addr) \
    asm volatile("ldmatrix.sync.aligned.m8n8.x4.trans.shared.b16 {%0,%1,%2,%3}, [%4];" \
                 : "=r"(r0), "=r"(r1), "=r"(r2), "=r"(r3) : "r"(addr))

__device__ __forceinline__ void cp16s(uint32_t saddr, const void* g) {
    asm volatile("cp.async.cg.shared.global [%0], [%1], 16;" :: "r"(saddr), "l"(g));
}
#define CP_COMMIT() asm volatile("cp.async.commit_group;")
#define CP_WAIT2()  asm volatile("cp.async.wait_group 2;")

__device__ __forceinline__ uint32_t smem_u32(const void* p) {
    return (uint32_t)__cvta_generic_to_shared(p);
}

// ---------------------------------------------------------------------------
// Fused prep: blocks [0, Bb*Cc) do pool+x->fp16; the rest convert Wq/Wk.
// ---------------------------------------------------------------------------
#define POOL_BLOCKS (Bb * Cc)
#define CONVW_BLOCKS ((N8 * Nn / 4) / 256)

__global__ void prep_kernel(const float* __restrict__ x,
                            const float* __restrict__ Wq,
                            const float* __restrict__ Wk) {
    if (blockIdx.x < POOL_BLOCKS) {
        int row = blockIdx.x;  // b*Cc + c
        const float4* xr = (const float4*)(x + (size_t)row * Nn);
        uint2* xh = (uint2*)(g_xh + (size_t)row * Nn);
        float m = -3.0e38f;
        for (int i = threadIdx.x; i < Nn / 4; i += 256) {
            float4 v = xr[i];
            __half2 p01 = __floats2half2_rn(v.x, v.y);
            __half2 p23 = __floats2half2_rn(v.z, v.w);
            uint2 u;
            u.x = *reinterpret_cast<uint32_t*>(&p01);
            u.y = *reinterpret_cast<uint32_t*>(&p23);
            xh[i] = u;
            m = fmaxf(m, fmaxf(fmaxf(v.x, v.y), fmaxf(v.z, v.w)));
        }
        m = warpMax(m);
        __shared__ float sm[8];
        if ((threadIdx.x & 31) == 0) sm[threadIdx.x >> 5] = m;
        __syncthreads();
        if (threadIdx.x == 0) {
            float r = sm[0];
#pragma unroll
            for (int i = 1; i < 8; i++) r = fmaxf(r, sm[i]);
            g_pooled[row] = r;
        }
    } else {
        int i = (blockIdx.x - POOL_BLOCKS) * 256 + threadIdx.x;
        float4 q = ((const float4*)Wq)[i];
        float4 k = ((const float4*)Wk)[i];
        __half2 q01 = __floats2half2_rn(q.x, q.y), q23 = __floats2half2_rn(q.z, q.w);
        __half2 k01 = __floats2half2_rn(k.x, k.y), k23 = __floats2half2_rn(k.z, k.w);
        uint2 uq, uk;
        uq.x = *reinterpret_cast<uint32_t*>(&q01); uq.y = *reinterpret_cast<uint32_t*>(&q23);
        uk.x = *reinterpret_cast<uint32_t*>(&k01); uk.y = *reinterpret_cast<uint32_t*>(&k23);
        ((uint2*)g_Wqh)[i] = uq;
        ((uint2*)g_Wkh)[i] = uk;
    }
}

// ---------------------------------------------------------------------------
__global__ void se_kernel(const float* __restrict__ W1, const float* __restrict__ W2) {
    int b = blockIdx.x;
    int t = threadIdx.x;
    __shared__ float h[32];
    if (t < 32) {
        float acc = 0.f;
        const float* w = W1 + t * Cc;
        const float* p = g_pooled + b * Cc;
        for (int c = 0; c < Cc; c++) acc += w[c] * p[c];
        h[t] = fmaxf(acc, 0.f);
    }
    __syncthreads();
    float acc = 0.f;
    const float* w2 = W2 + t * 32;
#pragma unroll
    for (int j = 0; j < 32; j++) acc += w2[j] * h[j];
    g_s[b * Cc + t] = 1.f / (1.f + expf(-acc));
}

// ---------------------------------------------------------------------------
// fp16 q/k GEMM: R8-proven config. Block 128x128, 4 warps of 64x64, kc=32,
// 4-stage cp.async, wait_group 2, LDSM/MMA first, prefetch after, two barriers.
// ---------------------------------------------------------------------------
#define QK_ROWB 80
#define QK_OPB  10240       // 128 rows * 80 B
#define QK_STB  20480
#define QK_NCH  (Nn / 32)   // 128

__global__ __launch_bounds__(128, 2) void gemm_qk_f16(
    const float* __restrict__ gq, const float* __restrict__ bq,
    const float* __restrict__ mq, const float* __restrict__ vq,
    const float* __restrict__ gk, const float* __restrict__ bk,
    const float* __restrict__ mk, const float* __restrict__ vk) {
    extern __shared__ char rawsm[];
    const uint32_t sbase = smem_u32(rawsm);

    const int z = blockIdx.z;
    const int b = z >> 1;
    const int sel = z & 1;
    const int m0 = blockIdx.y * 128;
    const int n0 = blockIdx.x * 128;
    const int tid = threadIdx.x;
    const int lane = tid & 31, warp = tid >> 5;
    const int wm = (warp >> 1) * 64, wn = (warp & 1) * 64;
    const int g = lane >> 2, t4 = lane & 3;

    const int lrow = tid >> 1;
    const int lhalf = tid & 1;
    const __half* gW0 = (sel ? g_Wkh : g_Wqh) + (size_t)(m0 + lrow) * Nn + lhalf * 16;
    const __half* gW1 = gW0 + (size_t)64 * Nn;
    const __half* gX0 = g_xh + ((size_t)b * Cc + n0 + lrow) * Nn + lhalf * 16;
    const __half* gX1 = gX0 + (size_t)64 * Nn;
    const uint32_t sA0 = sbase + lrow * QK_ROWB + lhalf * 32;
    const uint32_t sA1 = sA0 + 64 * QK_ROWB;
    const uint32_t sB0 = sA0 + QK_OPB;
    const uint32_t sB1 = sB0 + 64 * QK_ROWB;

    const uint32_t aoff = (uint32_t)((wm + (lane & 7) + ((lane >> 3) & 1) * 8) * QK_ROWB
                                     + ((lane >> 4) & 1) * 16);
    const uint32_t boff = (uint32_t)((wn + (lane & 7) + ((lane >> 4) & 1) * 8) * QK_ROWB
                                     + ((lane >> 3) & 1) * 16);

#pragma unroll
    for (int s = 0; s < 3; s++) {
        uint32_t st = s * QK_STB;
        int koff = s * 32;
        cp16s(sA0 + st,      gW0 + koff);
        cp16s(sA0 + st + 16, gW0 + koff + 8);
        cp16s(sA1 + st,      gW1 + koff);
        cp16s(sA1 + st + 16, gW1 + koff + 8);
        cp16s(sB0 + st,      gX0 + koff);
        cp16s(sB0 + st + 16, gX0 + koff + 8);
        cp16s(sB1 + st,      gX1 + koff);
        cp16s(sB1 + st + 16, gX1 + koff + 8);
        CP_COMMIT();
    }

    float acc[4][8][4];
#pragma unroll
    for (int i = 0; i < 4; i++)
#pragma unroll
        for (int j = 0; j < 8; j++)
#pragma unroll
            for (int r = 0; r < 4; r++) acc[i][j][r] = 0.f;

    for (int c = 0; c < QK_NCH; c++) {
        CP_WAIT2();
        __syncthreads();
        const uint32_t st = (c & 3) * QK_STB;
        const uint32_t Ab = sbase + st;
        const uint32_t Bbp = Ab + QK_OPB;
#pragma unroll
        for (int ks = 0; ks < 2; ks++) {
            uint32_t af[4][4], bfr[8][2];
#pragma unroll
            for (int mi = 0; mi < 4; mi++)
                LDSM_X4(af[mi][0], af[mi][1], af[mi][2], af[mi][3],
                        Ab + aoff + mi * (16 * QK_ROWB) + ks * 32);
#pragma unroll
            for (int nj = 0; nj < 4; nj++) {
                uint32_t r0, r1, r2, r3;
                LDSM_X4(r0, r1, r2, r3, Bbp + boff + nj * (16 * QK_ROWB) + ks * 32);
                bfr[2 * nj][0] = r0; bfr[2 * nj][1] = r1;
                bfr[2 * nj + 1][0] = r2; bfr[2 * nj + 1][1] = r3;
            }
#pragma unroll
            for (int mi = 0; mi < 4; mi++)
#pragma unroll
                for (int ni = 0; ni < 8; ni++)
                    mma_f16(acc[mi][ni], af[mi], bfr[ni]);
        }
        int nx = c + 3;
        if (nx < QK_NCH) {
            uint32_t s2 = (nx & 3) * QK_STB;
            int koff = nx * 32;
            cp16s(sA0 + s2,      gW0 + koff);
            cp16s(sA0 + s2 + 16, gW0 + koff + 8);
            cp16s(sA1 + s2,      gW1 + koff);
            cp16s(sA1 + s2 + 16, gW1 + koff + 8);
            cp16s(sB0 + s2,      gX0 + koff);
            cp16s(sB0 + s2 + 16, gX0 + koff + 8);
            cp16s(sB1 + s2,      gX1 + koff);
            cp16s(sB1 + s2 + 16, gX1 + koff + 8);
        }
        CP_COMMIT();
        __syncthreads();
    }

    const float* gg  = sel ? gk : gq;
    const float* bbp = sel ? bk : bq;
    const float* mmp = sel ? mk : mq;
    const float* vvp = sel ? vk : vq;
    __half* outp = sel ? g_kh : g_qh;
#pragma unroll
    for (int mi = 0; mi < 4; mi++) {
        int r0 = m0 + wm + mi * 16 + g;
        int r1 = r0 + 8;
        float sc0 = gg[r0] * rsqrtf(vvp[r0] + EPSf);
        float sh0 = bbp[r0] - mmp[r0] * sc0;
        float sc1 = gg[r1] * rsqrtf(vvp[r1] + EPSf);
        float sh1 = bbp[r1] - mmp[r1] * sc1;
#pragma unroll
        for (int ni = 0; ni < 8; ni++) {
            int cn = n0 + wn + ni * 8 + 2 * t4;
            __half2 h0 = __floats2half2_rn(fmaxf(acc[mi][ni][0] * sc0 + sh0, 0.f),
                                           fmaxf(acc[mi][ni][1] * sc0 + sh0, 0.f));
            __half2 h1 = __floats2half2_rn(fmaxf(acc[mi][ni][2] * sc1 + sh1, 0.f),
                                           fmaxf(acc[mi][ni][3] * sc1 + sh1, 0.f));
            *(__half2*)&outp[((size_t)b * N8 + r0) * Cc + cn] = h0;
            *(__half2*)&outp[((size_t)b * N8 + r1) * Cc + cn] = h1;
        }
    }
}

// ---------------------------------------------------------------------------
// sim[b,c,d] -- R10-proven retile: 64x128 block, 128 threads (4 warps 32x64),
// grid 256 CTAs, fp16 mma + trans ldmatrix.
// ---------------------------------------------------------------------------
#define SIM_AROWB 144               // 64 halves + 16B pad
#define SIM_BROWB 272               // 128 halves + 16B pad
#define SIM_APB   (32 * SIM_AROWB)  // 4608
#define SIM_BPB   (32 * SIM_BROWB)  // 8704
#define SIM_STB   (SIM_APB + SIM_BPB)  // 13312
#define SIM_NCH   (N8 / 32)         // 16

__global__ __launch_bounds__(128, 4) void gemm_sim_f16(void) {
    extern __shared__ char rawsm[];
    const uint32_t sbase = smem_u32(rawsm);

    const int b = blockIdx.z;
    const int c0 = blockIdx.y * 64;
    const int d0 = blockIdx.x * 128;
    const int tid = threadIdx.x;
    const int lane = tid & 31, warp = tid >> 5;
    const int wm = (warp >> 1) * 32, wn = (warp & 1) * 64;
    const int g = lane >> 2, t4 = lane & 3;

    const int arow = tid >> 2;
    const int aseg = tid & 3;
    const __half* gK = g_kh + ((size_t)b * N8 + arow) * Cc + c0 + aseg * 8;
    const uint32_t sA = sbase + arow * SIM_AROWB + aseg * 16;
    const int brow = tid >> 4;
    const int bseg = tid & 15;
    const __half* gQ = g_qh + ((size_t)b * N8 + brow) * Cc + d0 + bseg * 8;
    const uint32_t sB = sbase + SIM_APB + brow * SIM_BROWB + bseg * 16;
    const size_t qrow8 = (size_t)8 * Cc;

    const uint32_t aoffT = (uint32_t)(((lane & 7) + ((lane >> 4) & 1) * 8) * SIM_AROWB
                                      + (wm + ((lane >> 3) & 1) * 8) * 2);
    const uint32_t boffT = (uint32_t)(((lane & 7) + ((lane >> 3) & 1) * 8) * SIM_BROWB
                                      + (wn + ((lane >> 4) & 1) * 8) * 2);

#pragma unroll
    for (int s = 0; s < 3; s++) {
        uint32_t st = s * SIM_STB;
        size_t koff = (size_t)s * 32 * Cc;
        cp16s(sA + st,      gK + koff);
        cp16s(sA + st + 64, gK + koff + 32);
#pragma unroll
        for (int j = 0; j < 4; j++)
            cp16s(sB + st + j * (8 * SIM_BROWB), gQ + koff + j * qrow8);
        CP_COMMIT();
    }

    float acc[2][8][4];
#pragma unroll
    for (int i = 0; i < 2; i++)
#pragma unroll
        for (int j = 0; j < 8; j++)
#pragma unroll
            for (int rr = 0; rr < 4; rr++) acc[i][j][rr] = 0.f;

    for (int c = 0; c < SIM_NCH; c++) {
        CP_WAIT2();
        __syncthreads();
        const uint32_t st = (c & 3) * SIM_STB;
        const uint32_t Ab = sbase + st;
        const uint32_t Bbp = sbase + SIM_APB + st;
#pragma unroll
        for (int ks = 0; ks < 2; ks++) {
            uint32_t af[2][4], bfr[8][2];
#pragma unroll
            for (int mi = 0; mi < 2; mi++)
                LDSM_X4_T(af[mi][0], af[mi][1], af[mi][2], af[mi][3],
                          Ab + aoffT + ks * (16 * SIM_AROWB) + mi * 32);
#pragma unroll
            for (int nj = 0; nj < 4; nj++) {
                uint32_t r0, r1, r2, r3;
                LDSM_X4_T(r0, r1, r2, r3,
                          Bbp + boffT + ks * (16 * SIM_BROWB) + nj * 32);
                bfr[2 * nj][0] = r0; bfr[2 * nj][1] = r1;
                bfr[2 * nj + 1][0] = r2; bfr[2 * nj + 1][1] = r3;
            }
#pragma unroll
            for (int mi = 0; mi < 2; mi++)
#pragma unroll
                for (int ni = 0; ni < 8; ni++)
                    mma_f16(acc[mi][ni], af[mi], bfr[ni]);
        }
        int nx = c + 3;
        if (nx < SIM_NCH) {
            uint32_t s2 = (nx & 3) * SIM_STB;
            size_t koff = (size_t)nx * 32 * Cc;
            cp16s(sA + s2,      gK + koff);
            cp16s(sA + s2 + 64, gK + koff + 32);
#pragma unroll
            for (int j = 0; j < 4; j++)
                cp16s(sB + s2 + j * (8 * SIM_BROWB), gQ + koff + j * qrow8);
        }
        CP_COMMIT();
        __syncthreads();
    }

#pragma unroll
    for (int mi = 0; mi < 2; mi++) {
        int r0 = c0 + wm + mi * 16 + g;
        int r1 = r0 + 8;
#pragma unroll
        for (int ni = 0; ni < 8; ni++) {
            int cn = d0 + wn + ni * 8 + 2 * t4;
            float* p0 = g_sim + ((size_t)b * Cc + r0) * Cc + cn;
            float* p1 = g_sim + ((size_t)b * Cc + r1) * Cc + cn;
            *(float2*)p0 = make_float2(acc[mi][ni][0], acc[mi][ni][1]);
            *(float2*)p1 = make_float2(acc[mi][ni][2], acc[mi][ni][3]);
        }
    }
}

// ---------------------------------------------------------------------------
// aff' = alpha * softmax_d(-sim) * s[b,d]  -> fp16 g_simh
// Warp-per-row, 8 rows/block, vectorized float4 loads + uint4 store.
// ---------------------------------------------------------------------------
__global__ void softmax_kernel(const float* __restrict__ alpha) {
    const int row0 = blockIdx.x * 8;
    const int b = row0 >> 8;         // 8 rows never straddle a batch (256 % 8 == 0)
    __shared__ float ssm[Cc];
    const int t = threadIdx.x;
    ssm[t] = g_s[b * Cc + t];
    __syncthreads();

    const int warp = t >> 5, lane = t & 31;
    const int row = row0 + warp;
    const float* p = g_sim + (size_t)row * Cc + lane * 8;
    float4 v0 = *(const float4*)p;
    float4 v1 = *(const float4*)(p + 4);
    float vv[8] = {-v0.x, -v0.y, -v0.z, -v0.w, -v1.x, -v1.y, -v1.z, -v1.w};
    float m = vv[0];
#pragma unroll
    for (int j = 1; j < 8; j++) m = fmaxf(m, vv[j]);
    m = warpMax(m);
    float e[8];
    float s = 0.f;
#pragma unroll
    for (int j = 0; j < 8; j++) { e[j] = expf(vv[j] - m); s += e[j]; }
    s = warpSum(s);
    const float inv = alpha[0] / s;
    __half o[8];
#pragma unroll
    for (int j = 0; j < 8; j++)
        o[j] = __float2half_rn(e[j] * inv * ssm[lane * 8 + j]);
    *(uint4*)&g_simh[(size_t)row * Cc + lane * 8] = *(uint4*)o;
}

// ---------------------------------------------------------------------------
// out[b,c,n] = sum_d aff'[b,c,d]*x[b,d,n] + x[b,c,n]   (fp16 mma)
// R11-proven shape (256 thr, 8 warps 64x32); residual read from fp32 x.
// ---------------------------------------------------------------------------
#define GO_AROWB 80
#define GO_APB   (128 * GO_AROWB)
#define GO_BROWB 272
#define GO_BPB   (32 * GO_BROWB)
#define GO_STB   (GO_APB + GO_BPB)
#define GO_NCH   (Cc / 32)

__global__ __launch_bounds__(256, 2) void gemm_out_f16(
    const float* __restrict__ x, float* __restrict__ out) {
    extern __shared__ char rawsm[];
    const uint32_t sbase = smem_u32(rawsm);

    const int b = blockIdx.z;
    const int m0 = blockIdx.y * 128;
    const int n0 = blockIdx.x * 128;
    const int tid = threadIdx.x;
    const int lane = tid & 31, warp = tid >> 5;
    const int wm = (warp >> 2) * 64, wn = (warp & 3) * 32;
    const int g = lane >> 2, t4 = lane & 3;

    const int arow = tid >> 1;
    const int apart = tid & 1;
    const __half* gA = g_simh + ((size_t)b * Cc + m0 + arow) * Cc + apart * 16;
    const uint32_t sA = sbase + arow * GO_AROWB + apart * 32;
    const int brow = tid >> 4;
    const int bseg = tid & 15;
    const __half* gB = g_xh + ((size_t)b * Cc + brow) * Nn + n0 + bseg * 8;
    const uint32_t sB = sbase + GO_APB + brow * GO_BROWB + bseg * 16;
    const size_t brstep16 = (size_t)16 * Nn;

    const uint32_t aoff = (uint32_t)((wm + (lane & 7) + ((lane >> 3) & 1) * 8) * GO_AROWB
                                     + ((lane >> 4) & 1) * 16);
    const uint32_t boffT = (uint32_t)(((lane & 7) + ((lane >> 3) & 1) * 8) * GO_BROWB
                                      + (wn + ((lane >> 4) & 1) * 8) * 2);

#pragma unroll
    for (int s = 0; s < 3; s++) {
        uint32_t st = s * GO_STB;
        cp16s(sA + st,      gA + s * 32);
        cp16s(sA + st + 16, gA + s * 32 + 8);
        size_t bk = (size_t)s * 32 * Nn;
        cp16s(sB + st, gB + bk);
        cp16s(sB + st + 16 * GO_BROWB, gB + bk + brstep16);
        CP_COMMIT();
    }

    float acc[4][4][4];
#pragma unroll
    for (int i = 0; i < 4; i++)
#pragma unroll
        for (int j = 0; j < 4; j++)
#pragma unroll
            for (int rr = 0; rr < 4; rr++) acc[i][j][rr] = 0.f;

    for (int c = 0; c < GO_NCH; c++) {
        CP_WAIT2();
        __syncthreads();
        const uint32_t st = (c & 3) * GO_STB;
        const uint32_t Ab = sbase + st;
        const uint32_t Bbp = sbase + GO_APB + st;
#pragma unroll
        for (int ks = 0; ks < 2; ks++) {
            uint32_t af[4][4], bfr[4][2];
#pragma unroll
            for (int mi = 0; mi < 4; mi++)
                LDSM_X4(af[mi][0], af[mi][1], af[mi][2], af[mi][3],
                        Ab + aoff + mi * (16 * GO_AROWB) + ks * 32);
#pragma unroll
            for (int nj = 0; nj < 2; nj++) {
                uint32_t r0, r1, r2, r3;
                LDSM_X4_T(r0, r1, r2, r3,
                          Bbp + boffT + ks * (16 * GO_BROWB) + nj * 32);
                bfr[2 * nj][0] = r0; bfr[2 * nj][1] = r1;
                bfr[2 * nj + 1][0] = r2; bfr[2 * nj + 1][1] = r3;
            }
#pragma unroll
            for (int mi = 0; mi < 4; mi++)
#pragma unroll
                for (int ni = 0; ni < 4; ni++)
                    mma_f16(acc[mi][ni], af[mi], bfr[ni]);
        }
        int nx = c + 3;
        if (nx < GO_NCH) {
            uint32_t s2 = (nx & 3) * GO_STB;
            cp16s(sA + s2,      gA + nx * 32);
            cp16s(sA + s2 + 16, gA + nx * 32 + 8);
            size_t bk = (size_t)nx * 32 * Nn;
            cp16s(sB + s2, gB + bk);
            cp16s(sB + s2 + 16 * GO_BROWB, gB + bk + brstep16);
        }
        CP_COMMIT();
        __syncthreads();
    }

#pragma unroll
    for (int mi = 0; mi < 4; mi++) {
        int r0 = m0 + wm + mi * 16 + g;
        int r1 = r0 + 8;
#pragma unroll
        for (int ni = 0; ni < 4; ni++) {
            int cn = n0 + wn + ni * 8 + 2 * t4;
            size_t a0 = ((size_t)b * Cc + r0) * Nn + cn;
            size_t a1 = ((size_t)b * Cc + r1) * Nn + cn;
            float2 x0 = *(const float2*)(x + a0);
            float2 x1 = *(const float2*)(x + a1);
            *(float2*)(out + a0) = make_float2(acc[mi][ni][0] + x0.x, acc[mi][ni][1] + x0.y);
            *(float2*)(out + a1) = make_float2(acc[mi][ni][2] + x1.x, acc[mi][ni][3] + x1.y);
        }
    }
}

// ---------------------------------------------------------------------------
extern "C" void kernel_launch(void* const* d_in, const int* in_sizes, int n_in,
                              void* d_out, int out_size) {
    const float* x    = (const float*)d_in[0];
    const float* Wq   = (const float*)d_in[1];
    const float* bn1g = (const float*)d_in[2];
    const float* bn1b = (const float*)d_in[3];
    const float* bn1m = (const float*)d_in[4];
    const float* bn1v = (const float*)d_in[5];
    const float* Wk   = (const float*)d_in[6];
    const float* bn2g = (const float*)d_in[7];
    const float* bn2b = (const float*)d_in[8];
    const float* bn2m = (const float*)d_in[9];
    const float* bn2v = (const float*)d_in[10];
    const float* W1   = (const float*)d_in[11];
    const float* W2   = (const float*)d_in[12];
    const float* alpha = (const float*)d_in[13];
    float* out = (float*)d_out;

    const int qk_smem  = 4 * QK_STB;    // 81920 B
    const int sim_smem = 4 * SIM_STB;   // 53248 B
    const int go_smem  = 4 * GO_STB;    // 75776 B
    cudaFuncSetAttribute(gemm_qk_f16,  cudaFuncAttributeMaxDynamicSharedMemorySize, qk_smem);
    cudaFuncSetAttribute(gemm_sim_f16, cudaFuncAttributeMaxDynamicSharedMemorySize, sim_smem);
    cudaFuncSetAttribute(gemm_out_f16, cudaFuncAttributeMaxDynamicSharedMemorySize, go_smem);

    prep_kernel<<<POOL_BLOCKS + CONVW_BLOCKS, 256>>>(x, Wq, Wk);
    se_kernel<<<Bb, 256>>>(W1, W2);

    dim3 g1(Cc / 128, N8 / 128, 2 * Bb);
    gemm_qk_f16<<<g1, 128, qk_smem>>>(bn1g, bn1b, bn1m, bn1v,
                                      bn2g, bn2b, bn2m, bn2v);

    dim3 g2(Cc / 128, Cc / 64, Bb);
    gemm_sim_f16<<<g2, 128, sim_smem>>>();

    softmax_kernel<<<Bb * Cc / 8, 256>>>(alpha);

    dim3 g3(Nn / 128, Cc / 128, Bb);
    gemm_out_f16<<<g3, 256, go_smem>>>(x, out);
}